// round 16
// baseline (speedup 1.0000x reference)
#include <cuda_runtime.h>
#include <cuda_fp16.h>
#include <cstdint>
#include <cstddef>

#define D_MODEL   2048
#define NUM_HEADS 16
#define QGROUPS   4
#define HEAD_DIM  128
#define BATCH     2
#define SEQ       2048
#define ROWS      (BATCH * SEQ)
#define KV_COLS   (QGROUPS * HEAD_DIM)
#define QKV_LD    3072      // packed q(2048) | k(512) | v(512)

// ---------------- scratch ----------------
__device__ __half g_xh[ROWS * D_MODEL];
__device__ __half g_wqkvt[QKV_LD * D_MODEL];
__device__ float  g_bqkv[QKV_LD];
__device__ __half g_wot[D_MODEL * D_MODEL];
__device__ __half g_qkvh[ROWS * QKV_LD];
__device__ __half g_attnh[ROWS * D_MODEL];

// ---------------- helpers ----------------
__device__ __forceinline__ void mma16(float* d, const uint32_t* a, const uint32_t* b) {
    asm volatile(
        "mma.sync.aligned.m16n8k16.row.col.f32.f16.f16.f32 "
        "{%0,%1,%2,%3}, {%4,%5,%6,%7}, {%8,%9}, {%0,%1,%2,%3};\n"
        : "+f"(d[0]), "+f"(d[1]), "+f"(d[2]), "+f"(d[3])
        : "r"(a[0]), "r"(a[1]), "r"(a[2]), "r"(a[3]), "r"(b[0]), "r"(b[1]));
}
__device__ __forceinline__ void ldm_x4(uint32_t* r, uint32_t a) {
    asm volatile("ldmatrix.sync.aligned.m8n8.x4.shared.b16 {%0,%1,%2,%3}, [%4];"
                 : "=r"(r[0]), "=r"(r[1]), "=r"(r[2]), "=r"(r[3]) : "r"(a));
}
__device__ __forceinline__ void ldm_x4t(uint32_t* r, uint32_t a) {
    asm volatile("ldmatrix.sync.aligned.m8n8.x4.trans.shared.b16 {%0,%1,%2,%3}, [%4];"
                 : "=r"(r[0]), "=r"(r[1]), "=r"(r[2]), "=r"(r[3]) : "r"(a));
}
__device__ __forceinline__ void cp16(void* smem, const void* gmem) {
    uint32_t s = (uint32_t)__cvta_generic_to_shared(smem);
    asm volatile("cp.async.cg.shared.global [%0], [%1], 16;\n" :: "r"(s), "l"(gmem));
}
__device__ __forceinline__ void cp_commit() { asm volatile("cp.async.commit_group;\n"); }
template<int N> __device__ __forceinline__ void cp_wait() {
    asm volatile("cp.async.wait_group %0;\n" :: "n"(N));
}
__device__ __forceinline__ uint32_t sm_u32(const void* p) {
    return (uint32_t)__cvta_generic_to_shared(p);
}
__device__ __forceinline__ uint32_t packh2(float a, float b) {
    __half2 h = __halves2half2(__float2half_rn(a), __float2half_rn(b));
    return *(uint32_t*)&h;
}
__device__ __forceinline__ float ex2(float x) {
    float y;
    asm("ex2.approx.f32 %0, %1;" : "=f"(y) : "f"(x));
    return y;
}

// ---------------- prepass (3 launches) ----------------
__global__ void f2h_kernel(const float* __restrict__ in, __half* __restrict__ out, int n) {
    int i = (blockIdx.x * blockDim.x + threadIdx.x) * 4;
    if (i < n) {
        float4 v = *(const float4*)&in[i];
        __half2 h0 = __floats2half2_rn(v.x, v.y);
        __half2 h1 = __floats2half2_rn(v.z, v.w);
        uint2 pk;
        pk.x = *(uint32_t*)&h0;
        pk.y = *(uint32_t*)&h1;
        *(uint2*)&out[i] = pk;
    }
}
__global__ void trans_all(const float* __restrict__ Wq, const float* __restrict__ Wk,
                          const float* __restrict__ Wv, const float* __restrict__ Wo,
                          __half* __restrict__ wqkvt, __half* __restrict__ wot,
                          float qscale) {
    const int z = blockIdx.z;
    const float* in; __half* out; int N; float sc = 1.f;
    if (z == 0)      { in = Wq; out = wqkvt;                  N = 2048; sc = qscale; }
    else if (z == 1) { in = Wk; out = wqkvt + 2048 * D_MODEL; N = 512; }
    else if (z == 2) { in = Wv; out = wqkvt + 2560 * D_MODEL; N = 512; }
    else             { in = Wo; out = wot;                    N = 2048; }
    const int n0 = blockIdx.x * 32;
    if (n0 >= N) return;
    const int k0 = blockIdx.y * 32;
    __shared__ float t[32][33];
    const int tx = threadIdx.x, ty = threadIdx.y;
    #pragma unroll
    for (int i = 0; i < 32; i += 8)
        t[ty + i][tx] = in[(size_t)(k0 + ty + i) * N + n0 + tx];
    __syncthreads();
    #pragma unroll
    for (int i = 0; i < 32; i += 8)
        out[(size_t)(n0 + ty + i) * D_MODEL + k0 + tx] = __float2half_rn(t[tx][ty + i] * sc);
}
__global__ void concat_bias(const float* __restrict__ bq, const float* __restrict__ bk,
                            const float* __restrict__ bv, float* __restrict__ out,
                            float qscale) {
    int i = blockIdx.x * blockDim.x + threadIdx.x;
    if (i < 2048)      out[i] = bq[i] * qscale;
    else if (i < 2560) out[i] = bk[i - 2048];
    else if (i < 3072) out[i] = bv[i - 2560];
}

// ============================================================================
// fp16 GEMM: CTA 128x128, 128 threads, 4 warps (2m x 2n) of 64x64 warp tiles,
// BK=32, 4-stage cp.async ring, one sync/iter, ldmatrix.
// __launch_bounds__(128,2): 2 CTAs/SM (8 warps/SM) with barrier decoupling.
// 64x64 tile -> 16 MAC/byte of crossbar (vs 10.7 for 32x64): crossbar floor
// per SM-iter drops 768->512 cyc for the same 512 HMMA.
// ============================================================================
#define GSTG 20480
#define GEMM_SMEM (4 * GSTG)

__global__ __launch_bounds__(128, 2) void gemm_h(
    const __half* __restrict__ A, const __half* __restrict__ Bt,
    const float* __restrict__ bias,
    float* __restrict__ Cf, __half* __restrict__ Ch,
    int M, int N, int K)
{
    extern __shared__ char smc[];

    const int tid = threadIdx.x, lane = tid & 31, wid = tid >> 5;
    const int gr = lane >> 2, tig = lane & 3;
    const int wm = wid >> 1, wn = wid & 1;
    const int brow = blockIdx.y * 128, bcol = blockIdx.x * 128;

    const __half* gA = A + (size_t)(brow + tid) * K;
    const __half* gB = Bt + (size_t)(bcol + tid) * K;

    const int aoff = (wm * 64 + (lane & 7) + ((lane >> 3) & 1) * 8) * 40 + (lane >> 4) * 8;
    const int boff = (wn * 64 + (lane & 7) + (lane >> 4) * 8) * 40 + ((lane >> 3) & 1) * 8;

    float acc[4][8][4] = {};
    const int NIT = K >> 5;

    auto load_stage = [&](int s) {
        char* base = smc + (s & 3) * GSTG;
        const int k0 = s * 32;
        __half* as = (__half*)base;
        __half* bs = (__half*)(base + 10240);
        #pragma unroll
        for (int i = 0; i < 4; i++) {
            cp16(&as[tid * 40 + 8 * i], gA + k0 + 8 * i);
            cp16(&bs[tid * 40 + 8 * i], gB + k0 + 8 * i);
        }
        cp_commit();
    };

    load_stage(0);
    load_stage(1);
    load_stage(2);

    for (int it = 0; it < NIT; it++) {
        if (it + 2 < NIT)      cp_wait<2>();
        else if (it + 1 < NIT) cp_wait<1>();
        else                   cp_wait<0>();
        __syncthreads();
        if (it + 3 < NIT) load_stage(it + 3);

        const char* base = smc + (it & 3) * GSTG;
        const uint32_t aaddr = sm_u32(base) + 2u * aoff;
        const uint32_t baddr = sm_u32(base + 10240) + 2u * boff;

        #pragma unroll
        for (int ks = 0; ks < 2; ks++) {
            uint32_t af[4][4];
            #pragma unroll
            for (int mt = 0; mt < 4; mt++)
                ldm_x4(af[mt], aaddr + mt * 1280 + ks * 32);
            #pragma unroll
            for (int ntp = 0; ntp < 4; ntp++) {
                uint32_t bf[4];
                ldm_x4(bf, baddr + ntp * 1280 + ks * 32);
                #pragma unroll
                for (int mt = 0; mt < 4; mt++) {
                    mma16(acc[mt][2 * ntp], af[mt], bf);
                    mma16(acc[mt][2 * ntp + 1], af[mt], bf + 2);
                }
            }
        }
    }

    #pragma unroll
    for (int mt = 0; mt < 4; mt++) {
        const int r0 = brow + wm * 64 + mt * 16 + gr;
        #pragma unroll
        for (int nt = 0; nt < 8; nt++) {
            const int c = bcol + wn * 64 + nt * 8 + 2 * tig;
            const float b0 = bias[c], b1 = bias[c + 1];
            const float v0 = acc[mt][nt][0] + b0, v1 = acc[mt][nt][1] + b1;
            const float v2 = acc[mt][nt][2] + b0, v3 = acc[mt][nt][3] + b1;
            if (Cf) {
                float2 p0; p0.x = v0; p0.y = v1;
                float2 p1; p1.x = v2; p1.y = v3;
                *(float2*)&Cf[(size_t)r0 * N + c] = p0;
                *(float2*)&Cf[(size_t)(r0 + 8) * N + c] = p1;
            } else {
                *(uint32_t*)&Ch[(size_t)r0 * N + c] = packh2(v0, v1);
                *(uint32_t*)&Ch[(size_t)(r0 + 8) * N + c] = packh2(v2, v3);
            }
        }
    }
}

// ============================================================================
// Flash attention v2 + GQA head pairing (exact R12 winner).
// ============================================================================
#define QTILE 34816
#define KVBUF 34816
#define ATT_SMEM (2 * QTILE + 2 * KVBUF)   // 139264 B

__global__ __launch_bounds__(256, 1) void attn_h(
    const __half* __restrict__ QKV, __half* __restrict__ O)
{
    extern __shared__ char smc[];
    __half* Qs1 = (__half*)smc;
    __half* Qs2 = (__half*)(smc + QTILE);

    const int tid = threadIdx.x, lane = tid & 31, wid = tid >> 5;
    const int gr = lane >> 2, tig = lane & 3;
    const int bgp = blockIdx.y;
    const int b = bgp >> 3;
    const int g = (bgp >> 1) & 3;
    const int p = bgp & 1;
    const int h1 = g * 4 + p * 2;
    const int q0 = blockIdx.x * 128;

    const size_t rowbase = (size_t)b * SEQ * QKV_LD;

    {
        const int qr = tid >> 1, qc = (tid & 1) * 64;
        const __half* qp1 = QKV + rowbase + (size_t)(q0 + qr) * QKV_LD + h1 * HEAD_DIM + qc;
        __half* qs1 = &Qs1[qr * 136 + qc];
        __half* qs2 = &Qs2[qr * 136 + qc];
        #pragma unroll
        for (int i = 0; i < 8; i++) cp16(qs1 + 8 * i, qp1 + 8 * i);
        #pragma unroll
        for (int i = 0; i < 8; i++) cp16(qs2 + 8 * i, qp1 + HEAD_DIM + 8 * i);
    }
    const int kvr = tid >> 2, kvc = (tid & 3) * 32;
    const __half* kbase = QKV + rowbase + (size_t)kvr * QKV_LD + 2048 + g * HEAD_DIM + kvc;
    {
        __half* ks = (__half*)(smc + 2 * QTILE) + kvr * 136 + kvc;
        __half* vs = (__half*)(smc + 2 * QTILE + 17408) + kvr * 136 + kvc;
        #pragma unroll
        for (int i = 0; i < 4; i++) cp16(ks + 8 * i, kbase + 8 * i);
        #pragma unroll
        for (int i = 0; i < 4; i++) cp16(vs + 8 * i, kbase + 512 + 8 * i);
        cp_commit();
    }

    const int qa_off = (wid * 16 + (lane & 7) + ((lane >> 3) & 1) * 8) * 136 + (lane >> 4) * 8;
    const uint32_t qaddr1 = sm_u32(Qs1) + 2u * qa_off;
    const uint32_t qaddr2 = sm_u32(Qs2) + 2u * qa_off;
    const int kb_off = ((lane & 7) + (lane >> 4) * 8) * 136 + ((lane >> 3) & 1) * 8;
    const int vb_off = ((lane & 7) + ((lane >> 3) & 1) * 8) * 136 + (lane >> 4) * 8;

    float oacc1[16][4] = {};
    float oacc2[16][4] = {};
    float m0 = -1e30f, m1 = -1e30f, l0 = 0.f, l1 = 0.f;
    float m2 = -1e30f, m3 = -1e30f, l2 = 0.f, l3 = 0.f;

    for (int it = 0; it < SEQ / 64; it++) {
        cp_wait<0>();
        __syncthreads();
        if (it + 1 < SEQ / 64) {
            const __half* kp = kbase + (size_t)(it + 1) * 64 * QKV_LD;
            char* bufc = smc + 2 * QTILE + ((it + 1) & 1) * KVBUF;
            __half* ks = (__half*)bufc + kvr * 136 + kvc;
            __half* vs = (__half*)(bufc + 17408) + kvr * 136 + kvc;
            #pragma unroll
            for (int i = 0; i < 4; i++) cp16(ks + 8 * i, kp + 8 * i);
            #pragma unroll
            for (int i = 0; i < 4; i++) cp16(vs + 8 * i, kp + 512 + 8 * i);
            cp_commit();
        }

        const char* bufc = smc + 2 * QTILE + (it & 1) * KVBUF;
        const uint32_t kaddr = sm_u32(bufc) + 2u * kb_off;
        const uint32_t vaddr = sm_u32(bufc + 17408) + 2u * vb_off;

        // ---- S phase: K fragment loaded once, feeds both heads ----
        float sacc1[8][4] = {};
        float sacc2[8][4] = {};
        #pragma unroll
        for (int ks = 0; ks < 8; ks++) {
            uint32_t aq1[4], aq2[4];
            ldm_x4(aq1, qaddr1 + ks * 32);
            ldm_x4(aq2, qaddr2 + ks * 32);
            #pragma unroll
            for (int ng = 0; ng < 4; ng++) {
                uint32_t bf[4];
                ldm_x4(bf, kaddr + ng * 16 * 272 + ks * 32);
                mma16(sacc1[2 * ng], aq1, bf); mma16(sacc1[2 * ng + 1], aq1, bf + 2);
                mma16(sacc2[2 * ng], aq2, bf); mma16(sacc2[2 * ng + 1], aq2, bf + 2);
            }
        }

        // ---- softmax head1 -> pa1 ----
        uint32_t pa1[4][4], pa2[4][4];
        {
            float mx0 = sacc1[0][0], mx1 = sacc1[0][2];
            #pragma unroll
            for (int nt = 0; nt < 8; nt++) {
                mx0 = fmaxf(mx0, fmaxf(sacc1[nt][0], sacc1[nt][1]));
                mx1 = fmaxf(mx1, fmaxf(sacc1[nt][2], sacc1[nt][3]));
            }
            mx0 = fmaxf(mx0, __shfl_xor_sync(0xffffffffu, mx0, 1));
            mx0 = fmaxf(mx0, __shfl_xor_sync(0xffffffffu, mx0, 2));
            mx1 = fmaxf(mx1, __shfl_xor_sync(0xffffffffu, mx1, 1));
            mx1 = fmaxf(mx1, __shfl_xor_sync(0xffffffffu, mx1, 2));
            const float m0n = fmaxf(m0, mx0), m1n = fmaxf(m1, mx1);
            const float c0 = ex2(m0 - m0n), c1 = ex2(m1 - m1n);
            float s0 = 0.f, s1 = 0.f;
            #pragma unroll
            for (int nt = 0; nt < 8; nt++) {
                sacc1[nt][0] = ex2(sacc1[nt][0] - m0n);
                sacc1[nt][1] = ex2(sacc1[nt][1] - m0n);
                sacc1[nt][2] = ex2(sacc1[nt][2] - m1n);
                sacc1[nt][3] = ex2(sacc1[nt][3] - m1n);
                s0 += sacc1[nt][0] + sacc1[nt][1];
                s1 += sacc1[nt][2] + sacc1[nt][3];
            }
            s0 += __shfl_xor_sync(0xffffffffu, s0, 1);
            s0 += __shfl_xor_sync(0xffffffffu, s0, 2);
            s1 += __shfl_xor_sync(0xffffffffu, s1, 1);
            s1 += __shfl_xor_sync(0xffffffffu, s1, 2);
            l0 = l0 * c0 + s0; l1 = l1 * c1 + s1;
            m0 = m0n; m1 = m1n;
            #pragma unroll
            for (int nt = 0; nt < 16; nt++) {
                oacc1[nt][0] *= c0; oacc1[nt][1] *= c0;
                oacc1[nt][2] *= c1; oacc1[nt][3] *= c1;
            }
            #pragma unroll
            for (int kk = 0; kk < 4; kk++) {
                pa1[kk][0] = packh2(sacc1[2 * kk][0],     sacc1[2 * kk][1]);
                pa1[kk][1] = packh2(sacc1[2 * kk][2],     sacc1[2 * kk][3]);
                pa1[kk][2] = packh2(sacc1[2 * kk + 1][0], sacc1[2 * kk + 1][1]);
                pa1[kk][3] = packh2(sacc1[2 * kk + 1][2], sacc1[2 * kk + 1][3]);
            }
        }
        // ---- softmax head2 -> pa2 ----
        {
            float mx0 = sacc2[0][0], mx1 = sacc2[0][2];
            #pragma unroll
            for (int nt = 0; nt < 8; nt++) {
                mx0 = fmaxf(mx0, fmaxf(sacc2[nt][0], sacc2[nt][1]));
                mx1 = fmaxf(mx1, fmaxf(sacc2[nt][2], sacc2[nt][3]));
            }
            mx0 = fmaxf(mx0, __shfl_xor_sync(0xffffffffu, mx0, 1));
            mx0 = fmaxf(mx0, __shfl_xor_sync(0xffffffffu, mx0, 2));
            mx1 = fmaxf(mx1, __shfl_xor_sync(0xffffffffu, mx1, 1));
            mx1 = fmaxf(mx1, __shfl_xor_sync(0xffffffffu, mx1, 2));
            const float m2n = fmaxf(m2, mx0), m3n = fmaxf(m3, mx1);
            const float c2 = ex2(m2 - m2n), c3 = ex2(m3 - m3n);
            float s2 = 0.f, s3 = 0.f;
            #pragma unroll
            for (int nt = 0; nt < 8; nt++) {
                sacc2[nt][0] = ex2(sacc2[nt][0] - m2n);
                sacc2[nt][1] = ex2(sacc2[nt][1] - m2n);
                sacc2[nt][2] = ex2(sacc2[nt][2] - m3n);
                sacc2[nt][3] = ex2(sacc2[nt][3] - m3n);
                s2 += sacc2[nt][0] + sacc2[nt][1];
                s3 += sacc2[nt][2] + sacc2[nt][3];
            }
            s2 += __shfl_xor_sync(0xffffffffu, s2, 1);
            s2 += __shfl_xor_sync(0xffffffffu, s2, 2);
            s3 += __shfl_xor_sync(0xffffffffu, s3, 1);
            s3 += __shfl_xor_sync(0xffffffffu, s3, 2);
            l2 = l2 * c2 + s2; l3 = l3 * c3 + s3;
            m2 = m2n; m3 = m3n;
            #pragma unroll
            for (int nt = 0; nt < 16; nt++) {
                oacc2[nt][0] *= c2; oacc2[nt][1] *= c2;
                oacc2[nt][2] *= c3; oacc2[nt][3] *= c3;
            }
            #pragma unroll
            for (int kk = 0; kk < 4; kk++) {
                pa2[kk][0] = packh2(sacc2[2 * kk][0],     sacc2[2 * kk][1]);
                pa2[kk][1] = packh2(sacc2[2 * kk][2],     sacc2[2 * kk][3]);
                pa2[kk][2] = packh2(sacc2[2 * kk + 1][0], sacc2[2 * kk + 1][1]);
                pa2[kk][3] = packh2(sacc2[2 * kk + 1][2], sacc2[2 * kk + 1][3]);
            }
        }

        // ---- joint PV: V fragment loaded once, used by BOTH heads ----
        #pragma unroll
        for (int kk = 0; kk < 4; kk++) {
            #pragma unroll
            for (int ng = 0; ng < 8; ng++) {
                uint32_t vf[4];
                ldm_x4t(vf, vaddr + kk * 16 * 272 + ng * 32);
                mma16(oacc1[2 * ng], pa1[kk], vf);
                mma16(oacc1[2 * ng + 1], pa1[kk], vf + 2);
                mma16(oacc2[2 * ng], pa2[kk], vf);
                mma16(oacc2[2 * ng + 1], pa2[kk], vf + 2);
            }
        }
    }

    // ---- finalize both heads ----
    const int r0 = q0 + wid * 16 + gr;
    {
        const float il0 = 1.f / l0, il1 = 1.f / l1;
        __half* o0 = O + (size_t)(b * SEQ + r0) * D_MODEL + h1 * HEAD_DIM;
        __half* o1 = O + (size_t)(b * SEQ + r0 + 8) * D_MODEL + h1 * HEAD_DIM;
        #pragma unroll
        for (int nt = 0; nt < 16; nt++) {
            const int c = nt * 8 + 2 * tig;
            *(uint32_t*)&o0[c] = packh2(oacc1[nt][0] * il0, oacc1[nt][1] * il0);
            *(uint32_t*)&o1[c] = packh2(oacc1[nt][2] * il1, oacc1[nt][3] * il1);
        }
    }
    {
        const float il2 = 1.f / l2, il3 = 1.f / l3;
        __half* o0 = O + (size_t)(b * SEQ + r0) * D_MODEL + (h1 + 1) * HEAD_DIM;
        __half* o1 = O + (size_t)(b * SEQ + r0 + 8) * D_MODEL + (h1 + 1) * HEAD_DIM;
        #pragma unroll
        for (int nt = 0; nt < 16; nt++) {
            const int c = nt * 8 + 2 * tig;
            *(uint32_t*)&o0[c] = packh2(oacc2[nt][0] * il2, oacc2[nt][1] * il2);
            *(uint32_t*)&o1[c] = packh2(oacc2[nt][2] * il3, oacc2[nt][3] * il3);
        }
    }
}

// ============================================================================
extern "C" void kernel_launch(void* const* d_in, const int* in_sizes, int n_in,
                              void* d_out, int out_size)
{
    const float* x  = (const float*)d_in[0];
    const float* Wq = (const float*)d_in[1];
    const float* bq = (const float*)d_in[2];
    const float* Wk = (const float*)d_in[3];
    const float* bk = (const float*)d_in[4];
    const float* Wv = (const float*)d_in[5];
    const float* bv = (const float*)d_in[6];
    const float* Wo = (const float*)d_in[7];
    const float* bo = (const float*)d_in[8];
    float* out = (float*)d_out;

    __half *xh, *wqkvt, *wot, *qkvh, *attnh;
    float *bqkv;
    cudaGetSymbolAddress((void**)&xh, g_xh);
    cudaGetSymbolAddress((void**)&wqkvt, g_wqkvt);
    cudaGetSymbolAddress((void**)&bqkv, g_bqkv);
    cudaGetSymbolAddress((void**)&wot, g_wot);
    cudaGetSymbolAddress((void**)&qkvh, g_qkvh);
    cudaGetSymbolAddress((void**)&attnh, g_attnh);

    cudaFuncSetAttribute(gemm_h, cudaFuncAttributeMaxDynamicSharedMemorySize, GEMM_SMEM);
    cudaFuncSetAttribute(attn_h, cudaFuncAttributeMaxDynamicSharedMemorySize, ATT_SMEM);

    const float qscale = 0.08838834764831845f * 1.4426950408889634f;
    const int NX = ROWS * D_MODEL;

    f2h_kernel<<<NX / 1024, 256>>>(x, xh, NX);
    trans_all<<<dim3(64, 64, 4), dim3(32, 8)>>>(Wq, Wk, Wv, Wo, wqkvt, wot, qscale);
    concat_bias<<<QKV_LD / 256, 256>>>(bq, bk, bv, bqkv, qscale);

    gemm_h<<<dim3(QKV_LD / 128, ROWS / 128), 128, GEMM_SMEM>>>(
        xh, wqkvt, bqkv, nullptr, qkvh, ROWS, QKV_LD, D_MODEL);

    attn_h<<<dim3(SEQ / 128, 16), 256, ATT_SMEM>>>(qkvh, attnh);

    gemm_h<<<dim3(D_MODEL / 128, ROWS / 128), 128, GEMM_SMEM>>>(
        attnh, wot, bo, out, nullptr, ROWS, D_MODEL, D_MODEL);
}

// round 17
// speedup vs baseline: 1.1095x; 1.1095x over previous
#include <cuda_runtime.h>
#include <cuda_fp16.h>
#include <cstdint>
#include <cstddef>

#define D_MODEL   2048
#define NUM_HEADS 16
#define QGROUPS   4
#define HEAD_DIM  128
#define BATCH     2
#define SEQ       2048
#define ROWS      (BATCH * SEQ)
#define KV_COLS   (QGROUPS * HEAD_DIM)
#define QKV_LD    3072      // packed q(2048) | k(512) | v(512)

// ---------------- scratch ----------------
__device__ __half g_xh[ROWS * D_MODEL];
__device__ __half g_wqkvt[QKV_LD * D_MODEL];
__device__ float  g_bqkv[QKV_LD];
__device__ __half g_wot[D_MODEL * D_MODEL];
__device__ __half g_qkvh[ROWS * QKV_LD];
__device__ __half g_attnh[ROWS * D_MODEL];

// ---------------- helpers ----------------
__device__ __forceinline__ void mma16(float* d, const uint32_t* a, const uint32_t* b) {
    asm volatile(
        "mma.sync.aligned.m16n8k16.row.col.f32.f16.f16.f32 "
        "{%0,%1,%2,%3}, {%4,%5,%6,%7}, {%8,%9}, {%0,%1,%2,%3};\n"
        : "+f"(d[0]), "+f"(d[1]), "+f"(d[2]), "+f"(d[3])
        : "r"(a[0]), "r"(a[1]), "r"(a[2]), "r"(a[3]), "r"(b[0]), "r"(b[1]));
}
__device__ __forceinline__ void ldm_x4(uint32_t* r, uint32_t a) {
    asm volatile("ldmatrix.sync.aligned.m8n8.x4.shared.b16 {%0,%1,%2,%3}, [%4];"
                 : "=r"(r[0]), "=r"(r[1]), "=r"(r[2]), "=r"(r[3]) : "r"(a));
}
__device__ __forceinline__ void ldm_x4t(uint32_t* r, uint32_t a) {
    asm volatile("ldmatrix.sync.aligned.m8n8.x4.trans.shared.b16 {%0,%1,%2,%3}, [%4];"
                 : "=r"(r[0]), "=r"(r[1]), "=r"(r[2]), "=r"(r[3]) : "r"(a));
}
__device__ __forceinline__ void cp16(void* smem, const void* gmem) {
    uint32_t s = (uint32_t)__cvta_generic_to_shared(smem);
    asm volatile("cp.async.cg.shared.global [%0], [%1], 16;\n" :: "r"(s), "l"(gmem));
}
__device__ __forceinline__ void cp_commit() { asm volatile("cp.async.commit_group;\n"); }
template<int N> __device__ __forceinline__ void cp_wait() {
    asm volatile("cp.async.wait_group %0;\n" :: "n"(N));
}
__device__ __forceinline__ uint32_t sm_u32(const void* p) {
    return (uint32_t)__cvta_generic_to_shared(p);
}
__device__ __forceinline__ uint32_t packh2(float a, float b) {
    __half2 h = __halves2half2(__float2half_rn(a), __float2half_rn(b));
    return *(uint32_t*)&h;
}
__device__ __forceinline__ float ex2(float x) {
    float y;
    asm("ex2.approx.f32 %0, %1;" : "=f"(y) : "f"(x));
    return y;
}

// ---------------- prepass (3 launches) ----------------
__global__ void f2h_kernel(const float* __restrict__ in, __half* __restrict__ out, int n) {
    int i = (blockIdx.x * blockDim.x + threadIdx.x) * 4;
    if (i < n) {
        float4 v = *(const float4*)&in[i];
        __half2 h0 = __floats2half2_rn(v.x, v.y);
        __half2 h1 = __floats2half2_rn(v.z, v.w);
        uint2 pk;
        pk.x = *(uint32_t*)&h0;
        pk.y = *(uint32_t*)&h1;
        *(uint2*)&out[i] = pk;
    }
}
__global__ void trans_all(const float* __restrict__ Wq, const float* __restrict__ Wk,
                          const float* __restrict__ Wv, const float* __restrict__ Wo,
                          __half* __restrict__ wqkvt, __half* __restrict__ wot,
                          float qscale) {
    const int z = blockIdx.z;
    const float* in; __half* out; int N; float sc = 1.f;
    if (z == 0)      { in = Wq; out = wqkvt;                  N = 2048; sc = qscale; }
    else if (z == 1) { in = Wk; out = wqkvt + 2048 * D_MODEL; N = 512; }
    else if (z == 2) { in = Wv; out = wqkvt + 2560 * D_MODEL; N = 512; }
    else             { in = Wo; out = wot;                    N = 2048; }
    const int n0 = blockIdx.x * 32;
    if (n0 >= N) return;
    const int k0 = blockIdx.y * 32;
    __shared__ float t[32][33];
    const int tx = threadIdx.x, ty = threadIdx.y;
    #pragma unroll
    for (int i = 0; i < 32; i += 8)
        t[ty + i][tx] = in[(size_t)(k0 + ty + i) * N + n0 + tx];
    __syncthreads();
    #pragma unroll
    for (int i = 0; i < 32; i += 8)
        out[(size_t)(n0 + ty + i) * D_MODEL + k0 + tx] = __float2half_rn(t[tx][ty + i] * sc);
}
__global__ void concat_bias(const float* __restrict__ bq, const float* __restrict__ bk,
                            const float* __restrict__ bv, float* __restrict__ out,
                            float qscale) {
    int i = blockIdx.x * blockDim.x + threadIdx.x;
    if (i < 2048)      out[i] = bq[i] * qscale;
    else if (i < 2560) out[i] = bk[i - 2048];
    else if (i < 3072) out[i] = bv[i - 2560];
}

// ============================================================================
// fp16 GEMM (exact R12 winner): CTA 128x128, 256 thr, 8 warps (4m x 2n),
// warp tile 32x64, BK=32, 4-stage cp.async ring, one sync/iter, ldmatrix,
// __launch_bounds__(256,2) -> 2 CTAs/SM, 16 warps/SM.
// ============================================================================
#define GSTG 20480
#define GEMM_SMEM (4 * GSTG)

__global__ __launch_bounds__(256, 2) void gemm_h(
    const __half* __restrict__ A, const __half* __restrict__ Bt,
    const float* __restrict__ bias,
    float* __restrict__ Cf, __half* __restrict__ Ch,
    int M, int N, int K)
{
    extern __shared__ char smc[];

    const int tid = threadIdx.x, lane = tid & 31, wid = tid >> 5;
    const int gr = lane >> 2, tig = lane & 3;
    const int wm = wid >> 1, wn = wid & 1;
    const int brow = blockIdx.y * 128, bcol = blockIdx.x * 128;

    const int lrow = tid >> 1, lcol = (tid & 1) * 16;
    const __half* gA = A + (size_t)(brow + lrow) * K + lcol;
    const __half* gB = Bt + (size_t)(bcol + lrow) * K + lcol;

    const int aoff = (wm * 32 + (lane & 7) + ((lane >> 3) & 1) * 8) * 40 + (lane >> 4) * 8;
    const int boff = (wn * 64 + (lane & 7) + (lane >> 4) * 8) * 40 + ((lane >> 3) & 1) * 8;

    float acc[2][8][4] = {};
    const int NIT = K >> 5;

    auto load_stage = [&](int s) {
        char* base = smc + (s & 3) * GSTG;
        const int k0 = s * 32;
        __half* as = (__half*)base;
        __half* bs = (__half*)(base + 10240);
        cp16(&as[lrow * 40 + lcol], gA + k0);
        cp16(&as[lrow * 40 + lcol + 8], gA + k0 + 8);
        cp16(&bs[lrow * 40 + lcol], gB + k0);
        cp16(&bs[lrow * 40 + lcol + 8], gB + k0 + 8);
        cp_commit();
    };

    load_stage(0);
    load_stage(1);
    load_stage(2);

    for (int it = 0; it < NIT; it++) {
        if (it + 2 < NIT)      cp_wait<2>();
        else if (it + 1 < NIT) cp_wait<1>();
        else                   cp_wait<0>();
        __syncthreads();
        if (it + 3 < NIT) load_stage(it + 3);

        const char* base = smc + (it & 3) * GSTG;
        const uint32_t aaddr = sm_u32(base) + 2u * aoff;
        const uint32_t baddr = sm_u32(base + 10240) + 2u * boff;

        #pragma unroll
        for (int ks = 0; ks < 2; ks++) {
            uint32_t af[2][4];
            ldm_x4(af[0], aaddr + ks * 32);
            ldm_x4(af[1], aaddr + 1280 + ks * 32);
            #pragma unroll
            for (int ntp = 0; ntp < 4; ntp++) {
                uint32_t bf[4];
                ldm_x4(bf, baddr + ntp * 1280 + ks * 32);
                mma16(acc[0][2 * ntp], af[0], bf);
                mma16(acc[0][2 * ntp + 1], af[0], bf + 2);
                mma16(acc[1][2 * ntp], af[1], bf);
                mma16(acc[1][2 * ntp + 1], af[1], bf + 2);
            }
        }
    }

    #pragma unroll
    for (int mt = 0; mt < 2; mt++) {
        const int r0 = brow + wm * 32 + mt * 16 + gr;
        #pragma unroll
        for (int nt = 0; nt < 8; nt++) {
            const int c = bcol + wn * 64 + nt * 8 + 2 * tig;
            const float b0 = bias[c], b1 = bias[c + 1];
            const float v0 = acc[mt][nt][0] + b0, v1 = acc[mt][nt][1] + b1;
            const float v2 = acc[mt][nt][2] + b0, v3 = acc[mt][nt][3] + b1;
            if (Cf) {
                float2 p0; p0.x = v0; p0.y = v1;
                float2 p1; p1.x = v2; p1.y = v3;
                *(float2*)&Cf[(size_t)r0 * N + c] = p0;
                *(float2*)&Cf[(size_t)(r0 + 8) * N + c] = p1;
            } else {
                *(uint32_t*)&Ch[(size_t)r0 * N + c] = packh2(v0, v1);
                *(uint32_t*)&Ch[(size_t)(r0 + 8) * N + c] = packh2(v2, v3);
            }
        }
    }
}

// ============================================================================
// Flash attention v2 + GQA head pairing (exact R12 winner): two heads of the
// same KV group per CTA; K/V fragments loaded once feed both heads' MMAs.
// Br=128 (8 warps x 16 rows/head), Bc=64, register softmax, P in registers,
// one sync/iter, 2-stage KV ring, joint PV.
// ============================================================================
#define QTILE 34816
#define KVBUF 34816
#define ATT_SMEM (2 * QTILE + 2 * KVBUF)   // 139264 B

__global__ __launch_bounds__(256, 1) void attn_h(
    const __half* __restrict__ QKV, __half* __restrict__ O)
{
    extern __shared__ char smc[];
    __half* Qs1 = (__half*)smc;
    __half* Qs2 = (__half*)(smc + QTILE);

    const int tid = threadIdx.x, lane = tid & 31, wid = tid >> 5;
    const int gr = lane >> 2, tig = lane & 3;
    const int bgp = blockIdx.y;
    const int b = bgp >> 3;
    const int g = (bgp >> 1) & 3;
    const int p = bgp & 1;
    const int h1 = g * 4 + p * 2;
    const int q0 = blockIdx.x * 128;

    const size_t rowbase = (size_t)b * SEQ * QKV_LD;

    {
        const int qr = tid >> 1, qc = (tid & 1) * 64;
        const __half* qp1 = QKV + rowbase + (size_t)(q0 + qr) * QKV_LD + h1 * HEAD_DIM + qc;
        __half* qs1 = &Qs1[qr * 136 + qc];
        __half* qs2 = &Qs2[qr * 136 + qc];
        #pragma unroll
        for (int i = 0; i < 8; i++) cp16(qs1 + 8 * i, qp1 + 8 * i);
        #pragma unroll
        for (int i = 0; i < 8; i++) cp16(qs2 + 8 * i, qp1 + HEAD_DIM + 8 * i);
    }
    const int kvr = tid >> 2, kvc = (tid & 3) * 32;
    const __half* kbase = QKV + rowbase + (size_t)kvr * QKV_LD + 2048 + g * HEAD_DIM + kvc;
    {
        __half* ks = (__half*)(smc + 2 * QTILE) + kvr * 136 + kvc;
        __half* vs = (__half*)(smc + 2 * QTILE + 17408) + kvr * 136 + kvc;
        #pragma unroll
        for (int i = 0; i < 4; i++) cp16(ks + 8 * i, kbase + 8 * i);
        #pragma unroll
        for (int i = 0; i < 4; i++) cp16(vs + 8 * i, kbase + 512 + 8 * i);
        cp_commit();
    }

    const int qa_off = (wid * 16 + (lane & 7) + ((lane >> 3) & 1) * 8) * 136 + (lane >> 4) * 8;
    const uint32_t qaddr1 = sm_u32(Qs1) + 2u * qa_off;
    const uint32_t qaddr2 = sm_u32(Qs2) + 2u * qa_off;
    const int kb_off = ((lane & 7) + (lane >> 4) * 8) * 136 + ((lane >> 3) & 1) * 8;
    const int vb_off = ((lane & 7) + ((lane >> 3) & 1) * 8) * 136 + (lane >> 4) * 8;

    float oacc1[16][4] = {};
    float oacc2[16][4] = {};
    float m0 = -1e30f, m1 = -1e30f, l0 = 0.f, l1 = 0.f;
    float m2 = -1e30f, m3 = -1e30f, l2 = 0.f, l3 = 0.f;

    for (int it = 0; it < SEQ / 64; it++) {
        cp_wait<0>();
        __syncthreads();
        if (it + 1 < SEQ / 64) {
            const __half* kp = kbase + (size_t)(it + 1) * 64 * QKV_LD;
            char* bufc = smc + 2 * QTILE + ((it + 1) & 1) * KVBUF;
            __half* ks = (__half*)bufc + kvr * 136 + kvc;
            __half* vs = (__half*)(bufc + 17408) + kvr * 136 + kvc;
            #pragma unroll
            for (int i = 0; i < 4; i++) cp16(ks + 8 * i, kp + 8 * i);
            #pragma unroll
            for (int i = 0; i < 4; i++) cp16(vs + 8 * i, kp + 512 + 8 * i);
            cp_commit();
        }

        const char* bufc = smc + 2 * QTILE + (it & 1) * KVBUF;
        const uint32_t kaddr = sm_u32(bufc) + 2u * kb_off;
        const uint32_t vaddr = sm_u32(bufc + 17408) + 2u * vb_off;

        // ---- S phase: K fragment loaded once, feeds both heads ----
        float sacc1[8][4] = {};
        float sacc2[8][4] = {};
        #pragma unroll
        for (int ks = 0; ks < 8; ks++) {
            uint32_t aq1[4], aq2[4];
            ldm_x4(aq1, qaddr1 + ks * 32);
            ldm_x4(aq2, qaddr2 + ks * 32);
            #pragma unroll
            for (int ng = 0; ng < 4; ng++) {
                uint32_t bf[4];
                ldm_x4(bf, kaddr + ng * 16 * 272 + ks * 32);
                mma16(sacc1[2 * ng], aq1, bf); mma16(sacc1[2 * ng + 1], aq1, bf + 2);
                mma16(sacc2[2 * ng], aq2, bf); mma16(sacc2[2 * ng + 1], aq2, bf + 2);
            }
        }

        // ---- softmax head1 -> pa1 ----
        uint32_t pa1[4][4], pa2[4][4];
        {
            float mx0 = sacc1[0][0], mx1 = sacc1[0][2];
            #pragma unroll
            for (int nt = 0; nt < 8; nt++) {
                mx0 = fmaxf(mx0, fmaxf(sacc1[nt][0], sacc1[nt][1]));
                mx1 = fmaxf(mx1, fmaxf(sacc1[nt][2], sacc1[nt][3]));
            }
            mx0 = fmaxf(mx0, __shfl_xor_sync(0xffffffffu, mx0, 1));
            mx0 = fmaxf(mx0, __shfl_xor_sync(0xffffffffu, mx0, 2));
            mx1 = fmaxf(mx1, __shfl_xor_sync(0xffffffffu, mx1, 1));
            mx1 = fmaxf(mx1, __shfl_xor_sync(0xffffffffu, mx1, 2));
            const float m0n = fmaxf(m0, mx0), m1n = fmaxf(m1, mx1);
            const float c0 = ex2(m0 - m0n), c1 = ex2(m1 - m1n);
            float s0 = 0.f, s1 = 0.f;
            #pragma unroll
            for (int nt = 0; nt < 8; nt++) {
                sacc1[nt][0] = ex2(sacc1[nt][0] - m0n);
                sacc1[nt][1] = ex2(sacc1[nt][1] - m0n);
                sacc1[nt][2] = ex2(sacc1[nt][2] - m1n);
                sacc1[nt][3] = ex2(sacc1[nt][3] - m1n);
                s0 += sacc1[nt][0] + sacc1[nt][1];
                s1 += sacc1[nt][2] + sacc1[nt][3];
            }
            s0 += __shfl_xor_sync(0xffffffffu, s0, 1);
            s0 += __shfl_xor_sync(0xffffffffu, s0, 2);
            s1 += __shfl_xor_sync(0xffffffffu, s1, 1);
            s1 += __shfl_xor_sync(0xffffffffu, s1, 2);
            l0 = l0 * c0 + s0; l1 = l1 * c1 + s1;
            m0 = m0n; m1 = m1n;
            #pragma unroll
            for (int nt = 0; nt < 16; nt++) {
                oacc1[nt][0] *= c0; oacc1[nt][1] *= c0;
                oacc1[nt][2] *= c1; oacc1[nt][3] *= c1;
            }
            #pragma unroll
            for (int kk = 0; kk < 4; kk++) {
                pa1[kk][0] = packh2(sacc1[2 * kk][0],     sacc1[2 * kk][1]);
                pa1[kk][1] = packh2(sacc1[2 * kk][2],     sacc1[2 * kk][3]);
                pa1[kk][2] = packh2(sacc1[2 * kk + 1][0], sacc1[2 * kk + 1][1]);
                pa1[kk][3] = packh2(sacc1[2 * kk + 1][2], sacc1[2 * kk + 1][3]);
            }
        }
        // ---- softmax head2 -> pa2 ----
        {
            float mx0 = sacc2[0][0], mx1 = sacc2[0][2];
            #pragma unroll
            for (int nt = 0; nt < 8; nt++) {
                mx0 = fmaxf(mx0, fmaxf(sacc2[nt][0], sacc2[nt][1]));
                mx1 = fmaxf(mx1, fmaxf(sacc2[nt][2], sacc2[nt][3]));
            }
            mx0 = fmaxf(mx0, __shfl_xor_sync(0xffffffffu, mx0, 1));
            mx0 = fmaxf(mx0, __shfl_xor_sync(0xffffffffu, mx0, 2));
            mx1 = fmaxf(mx1, __shfl_xor_sync(0xffffffffu, mx1, 1));
            mx1 = fmaxf(mx1, __shfl_xor_sync(0xffffffffu, mx1, 2));
            const float m2n = fmaxf(m2, mx0), m3n = fmaxf(m3, mx1);
            const float c2 = ex2(m2 - m2n), c3 = ex2(m3 - m3n);
            float s2 = 0.f, s3 = 0.f;
            #pragma unroll
            for (int nt = 0; nt < 8; nt++) {
                sacc2[nt][0] = ex2(sacc2[nt][0] - m2n);
                sacc2[nt][1] = ex2(sacc2[nt][1] - m2n);
                sacc2[nt][2] = ex2(sacc2[nt][2] - m3n);
                sacc2[nt][3] = ex2(sacc2[nt][3] - m3n);
                s2 += sacc2[nt][0] + sacc2[nt][1];
                s3 += sacc2[nt][2] + sacc2[nt][3];
            }
            s2 += __shfl_xor_sync(0xffffffffu, s2, 1);
            s2 += __shfl_xor_sync(0xffffffffu, s2, 2);
            s3 += __shfl_xor_sync(0xffffffffu, s3, 1);
            s3 += __shfl_xor_sync(0xffffffffu, s3, 2);
            l2 = l2 * c2 + s2; l3 = l3 * c3 + s3;
            m2 = m2n; m3 = m3n;
            #pragma unroll
            for (int nt = 0; nt < 16; nt++) {
                oacc2[nt][0] *= c2; oacc2[nt][1] *= c2;
                oacc2[nt][2] *= c3; oacc2[nt][3] *= c3;
            }
            #pragma unroll
            for (int kk = 0; kk < 4; kk++) {
                pa2[kk][0] = packh2(sacc2[2 * kk][0],     sacc2[2 * kk][1]);
                pa2[kk][1] = packh2(sacc2[2 * kk][2],     sacc2[2 * kk][3]);
                pa2[kk][2] = packh2(sacc2[2 * kk + 1][0], sacc2[2 * kk + 1][1]);
                pa2[kk][3] = packh2(sacc2[2 * kk + 1][2], sacc2[2 * kk + 1][3]);
            }
        }

        // ---- joint PV: V fragment loaded once, used by BOTH heads ----
        #pragma unroll
        for (int kk = 0; kk < 4; kk++) {
            #pragma unroll
            for (int ng = 0; ng < 8; ng++) {
                uint32_t vf[4];
                ldm_x4t(vf, vaddr + kk * 16 * 272 + ng * 32);
                mma16(oacc1[2 * ng], pa1[kk], vf);
                mma16(oacc1[2 * ng + 1], pa1[kk], vf + 2);
                mma16(oacc2[2 * ng], pa2[kk], vf);
                mma16(oacc2[2 * ng + 1], pa2[kk], vf + 2);
            }
        }
    }

    // ---- finalize both heads ----
    const int r0 = q0 + wid * 16 + gr;
    {
        const float il0 = 1.f / l0, il1 = 1.f / l1;
        __half* o0 = O + (size_t)(b * SEQ + r0) * D_MODEL + h1 * HEAD_DIM;
        __half* o1 = O + (size_t)(b * SEQ + r0 + 8) * D_MODEL + h1 * HEAD_DIM;
        #pragma unroll
        for (int nt = 0; nt < 16; nt++) {
            const int c = nt * 8 + 2 * tig;
            *(uint32_t*)&o0[c] = packh2(oacc1[nt][0] * il0, oacc1[nt][1] * il0);
            *(uint32_t*)&o1[c] = packh2(oacc1[nt][2] * il1, oacc1[nt][3] * il1);
        }
    }
    {
        const float il2 = 1.f / l2, il3 = 1.f / l3;
        __half* o0 = O + (size_t)(b * SEQ + r0) * D_MODEL + (h1 + 1) * HEAD_DIM;
        __half* o1 = O + (size_t)(b * SEQ + r0 + 8) * D_MODEL + (h1 + 1) * HEAD_DIM;
        #pragma unroll
        for (int nt = 0; nt < 16; nt++) {
            const int c = nt * 8 + 2 * tig;
            *(uint32_t*)&o0[c] = packh2(oacc2[nt][0] * il2, oacc2[nt][1] * il2);
            *(uint32_t*)&o1[c] = packh2(oacc2[nt][2] * il3, oacc2[nt][3] * il3);
        }
    }
}

// ============================================================================
extern "C" void kernel_launch(void* const* d_in, const int* in_sizes, int n_in,
                              void* d_out, int out_size)
{
    const float* x  = (const float*)d_in[0];
    const float* Wq = (const float*)d_in[1];
    const float* bq = (const float*)d_in[2];
    const float* Wk = (const float*)d_in[3];
    const float* bk = (const float*)d_in[4];
    const float* Wv = (const float*)d_in[5];
    const float* bv = (const float*)d_in[6];
    const float* Wo = (const float*)d_in[7];
    const float* bo = (const float*)d_in[8];
    float* out = (float*)d_out;

    __half *xh, *wqkvt, *wot, *qkvh, *attnh;
    float *bqkv;
    cudaGetSymbolAddress((void**)&xh, g_xh);
    cudaGetSymbolAddress((void**)&wqkvt, g_wqkvt);
    cudaGetSymbolAddress((void**)&bqkv, g_bqkv);
    cudaGetSymbolAddress((void**)&wot, g_wot);
    cudaGetSymbolAddress((void**)&qkvh, g_qkvh);
    cudaGetSymbolAddress((void**)&attnh, g_attnh);

    cudaFuncSetAttribute(gemm_h, cudaFuncAttributeMaxDynamicSharedMemorySize, GEMM_SMEM);
    cudaFuncSetAttribute(attn_h, cudaFuncAttributeMaxDynamicSharedMemorySize, ATT_SMEM);

    const float qscale = 0.08838834764831845f * 1.4426950408889634f;
    const int NX = ROWS * D_MODEL;

    f2h_kernel<<<NX / 1024, 256>>>(x, xh, NX);
    trans_all<<<dim3(64, 64, 4), dim3(32, 8)>>>(Wq, Wk, Wv, Wo, wqkvt, wot, qscale);
    concat_bias<<<QKV_LD / 256, 256>>>(bq, bk, bv, bqkv, qscale);

    gemm_h<<<dim3(QKV_LD / 128, ROWS / 128), 256, GEMM_SMEM>>>(
        xh, wqkvt, bqkv, nullptr, qkvh, ROWS, QKV_LD, D_MODEL);

    attn_h<<<dim3(SEQ / 128, 16), 256, ATT_SMEM>>>(qkvh, attnh);

    gemm_h<<<dim3(D_MODEL / 128, ROWS / 128), 256, GEMM_SMEM>>>(
        attnh, wot, bo, out, nullptr, ROWS, D_MODEL, D_MODEL);
}